// round 13
// baseline (speedup 1.0000x reference)
#include <cuda_runtime.h>
#include <cuda_bf16.h>

#define TARWD_ALPHA 0.1f
#define TARWD_MAX_NODES (1 << 20)   // 4 MB per array

// g_deg: degree accumulator. INVARIANT: zero on entry to every kernel_launch
// (zero at module load; k_finalize re-zeros it each call) -> deterministic.
__device__ float g_deg[TARWD_MAX_NODES];
// g_dinv: deg^{-1/2} (0 for isolated nodes), produced by k_finalize
__device__ float g_dinv[TARWD_MAX_NODES];

static __device__ __forceinline__ int read_num_nodes(const int* nnp, int fallback) {
    return nnp ? *nnp : fallback;
}

// exp(x) for x in [0, 0.1]: degree-4 Taylor. |err| <= x^5/120 * e^0.1 ~ 9.2e-8.
static __device__ __forceinline__ float exp_small(float x) {
    const float c4 = 1.0f / 24.0f, c3 = 1.0f / 6.0f, c2 = 0.5f;
    float p = fmaf(x, c4, c3);
    p = fmaf(x, p, c2);
    p = fmaf(x, p, 1.0f);
    p = fmaf(x, p, 1.0f);
    return p;
}

// ---------------------------------------------------------------------------
// K1 (SLIM): deg[u_e] += exp(+alpha * t_e). Pure REDG drain — no copies
// (embedding them cost +6us from LSU/L1tex contention with the atomics).
// One edge-group per thread; no unroll (R4/R10: front-batched loads inflate
// cross-CTA L1tex queue contention).
__global__ void __launch_bounds__(256, 8)
k_degree(const int4* __restrict__ u4,
         const float4* __restrict__ t4, int n4) {
    const int i = blockIdx.x * blockDim.x + threadIdx.x;
    if (i >= n4) return;
    const int4   u = __ldcs(&u4[i]);
    const float4 t = __ldcs(&t4[i]);
    atomicAdd(&g_deg[u.x], exp_small(TARWD_ALPHA * t.x));
    atomicAdd(&g_deg[u.y], exp_small(TARWD_ALPHA * t.y));
    atomicAdd(&g_deg[u.z], exp_small(TARWD_ALPHA * t.z));
    atomicAdd(&g_deg[u.w], exp_small(TARWD_ALPHA * t.w));
}

// ---------------------------------------------------------------------------
// K2 (FAT): rsqrt+reset on nodes AND both index passthrough copies.
// The copies run here standalone: ei is L2-hot from k_degree (25.6MB << L2),
// so this is a pure streaming pass with nothing competing for LSU/L1tex.
// Thread i < nC4 copies one int4->float4 group; thread i < nq also handles
// one float4 node group. One shot, no loops (nC4 = 1.6M threads).
__global__ void __launch_bounds__(256, 8)
k_finalize(const int4* __restrict__ ei4,      // [2E] both halves contiguous
           float4* __restrict__ out_idx4,     // float(u),float(v) target
           int nC4,                           // 2*E4 copy groups
           const int* __restrict__ num_nodes_ptr, int nn_fallback) {
    const int i = blockIdx.x * blockDim.x + threadIdx.x;

    // index passthrough: int4 -> float4, streaming
    if (i < nC4) {
        const int4 e = __ldcs(&ei4[i]);
        __stcs(&out_idx4[i],
               make_float4((float)e.x, (float)e.y, (float)e.z, (float)e.w));
    }

    // node finalize: dinv = rsqrt(deg) or 0; reset deg for next replay
    const int n  = read_num_nodes(num_nodes_ptr, nn_fallback);
    const int nq = n >> 2;
    if (i < nq) {
        float4* deg4  = reinterpret_cast<float4*>(g_deg);
        float4* dinv4 = reinterpret_cast<float4*>(g_dinv);
        const float4 d = deg4[i];
        float4 r;
        r.x = (d.x > 0.0f) ? rsqrtf(d.x) : 0.0f;
        r.y = (d.y > 0.0f) ? rsqrtf(d.y) : 0.0f;
        r.z = (d.z > 0.0f) ? rsqrtf(d.z) : 0.0f;
        r.w = (d.w > 0.0f) ? rsqrtf(d.w) : 0.0f;
        dinv4[i] = r;
        deg4[i]  = make_float4(0.0f, 0.0f, 0.0f, 0.0f);
    } else if (i >= nq && i < nq + 4) {
        // scalar tail (n not divisible by 4), threads nq..nq+3
        const int k = (nq << 2) + (i - nq);
        if (k < n) {
            const float d = g_deg[k];
            g_dinv[k] = (d > 0.0f) ? rsqrtf(d) : 0.0f;
            g_deg[k]  = 0.0f;
        }
    }
}

// ---------------------------------------------------------------------------
// K3 (SLIM): w_e = dinv[u] * exp(alpha*t_e) * dinv[v].
// At the gather-wavefront floor; 8 independent scattered gathers.
__global__ void __launch_bounds__(256, 8)
k_weight(const int4* __restrict__ u4,
         const int4* __restrict__ v4,
         const float4* __restrict__ t4,
         float4* __restrict__ w4, int n4) {
    const int i = blockIdx.x * blockDim.x + threadIdx.x;
    if (i >= n4) return;
    const int4   u = __ldcs(&u4[i]);
    const int4   v = __ldcs(&v4[i]);
    const float4 t = __ldcs(&t4[i]);
    const float a0 = __ldg(&g_dinv[u.x]), a1 = __ldg(&g_dinv[u.y]);
    const float a2 = __ldg(&g_dinv[u.z]), a3 = __ldg(&g_dinv[u.w]);
    const float b0 = __ldg(&g_dinv[v.x]), b1 = __ldg(&g_dinv[v.y]);
    const float b2 = __ldg(&g_dinv[v.z]), b3 = __ldg(&g_dinv[v.w]);
    float4 w;
    w.x = a0 * exp_small(TARWD_ALPHA * t.x) * b0;
    w.y = a1 * exp_small(TARWD_ALPHA * t.y) * b1;
    w.z = a2 * exp_small(TARWD_ALPHA * t.z) * b2;
    w.w = a3 * exp_small(TARWD_ALPHA * t.w) * b3;
    __stcs(&w4[i], w);
}

// ---------------------------------------------------------------------------
extern "C" void kernel_launch(void* const* d_in, const int* in_sizes, int n_in,
                              void* d_out, int out_size) {
    const int*   ei = (const int*)d_in[0];     // [2, E]: u = ei[0..E), v = ei[E..2E)
    const float* et = (const float*)d_in[1];   // [E]
    const int*   nn = (n_in >= 3) ? (const int*)d_in[2] : nullptr;
    const int    nn_fallback = 100000;

    const int E  = in_sizes[1];
    const int E4 = E >> 2;                     // E = 3.2M -> E4 = 800000
    const int* u = ei;
    const int* v = ei + E;

    float* out   = (float*)d_out;
    float* out_w = out + (out_size - E);       // weights at the tail

    const int TB = 256;
    const int GE = (E4 + TB - 1) / TB;         // 3125: exact one-shot cover

    const bool full_out = (out_size >= 3 * E); // [float(u), float(v), w]
    // copy target: real passthrough slots, or out_w scratch (overwritten
    // afterwards by the weights) when no passthrough is required
    const int nC4 = full_out ? (2 * E4) : 0;   // skip copy entirely if unused
    float* out_idx = out;                      // [float(u) | float(v)] = out[0..2E)
    const int GF_work = (nC4 > 0) ? nC4 : (nn_fallback >> 2) + TB;
    const int GF = (GF_work + TB - 1) / TB;

    k_degree  <<<GE, TB>>>((const int4*)u, (const float4*)et, E4);
    k_finalize<<<GF, TB>>>((const int4*)ei, (float4*)out_idx, nC4,
                           nn, nn_fallback);
    k_weight  <<<GE, TB>>>((const int4*)u, (const int4*)v,
                           (const float4*)et, (float4*)out_w, E4);
}

// round 14
// speedup vs baseline: 1.0058x; 1.0058x over previous
#include <cuda_runtime.h>
#include <cuda_bf16.h>

#define TARWD_ALPHA 0.1f
#define TARWD_MAX_NODES (1 << 20)   // 4 MB per array

// g_deg: degree accumulator. INVARIANT: zero on entry to every kernel_launch
// (zero at module load; k_finalize re-zeros it each call) -> deterministic.
__device__ float g_deg[TARWD_MAX_NODES];
// g_dinv: deg^{-1/2} (0 for isolated nodes), produced by k_finalize
__device__ float g_dinv[TARWD_MAX_NODES];

static __device__ __forceinline__ int read_num_nodes(const int* nnp, int fallback) {
    return nnp ? *nnp : fallback;
}

// exp(x) for x in [0, 0.1]: degree-4 Taylor. |err| <= x^5/120 * e^0.1 ~ 9.2e-8.
static __device__ __forceinline__ float exp_small(float x) {
    const float c4 = 1.0f / 24.0f, c3 = 1.0f / 6.0f, c2 = 0.5f;
    float p = fmaf(x, c4, c3);
    p = fmaf(x, p, c2);
    p = fmaf(x, p, 1.0f);
    p = fmaf(x, p, 1.0f);
    return p;
}

// ---------------------------------------------------------------------------
// K1: deg[u_e] += exp(+alpha * t_e), absorbing ONLY the out_u copy.
// Copy-placement calibration (R12/R13): 1st copy embedded here is ~half
// hidden under the RED drain (+~2us); a 2nd copy costs more (+4.3 total),
// and standalone copies cost ~3.2us each. So: one copy here, one in K2.
__global__ void __launch_bounds__(256, 8)
k_degree(const int4* __restrict__ u4,
         const float4* __restrict__ t4,
         float4* __restrict__ out_u4, int n4) {
    const int i = blockIdx.x * blockDim.x + threadIdx.x;
    if (i >= n4) return;
    const int4   u = __ldcs(&u4[i]);
    const float4 t = __ldcs(&t4[i]);
    __stcs(&out_u4[i], make_float4((float)u.x, (float)u.y, (float)u.z, (float)u.w));
    atomicAdd(&g_deg[u.x], exp_small(TARWD_ALPHA * t.x));
    atomicAdd(&g_deg[u.y], exp_small(TARWD_ALPHA * t.y));
    atomicAdd(&g_deg[u.z], exp_small(TARWD_ALPHA * t.z));
    atomicAdd(&g_deg[u.w], exp_small(TARWD_ALPHA * t.w));
}

// ---------------------------------------------------------------------------
// K2: node finalize (dinv = rsqrt(deg) or 0; reset deg) + out_v copy.
// Thread i < nC4 copies one v int4->float4 group; low threads also do
// one float4 node group. One shot (nC4 = 800K threads covers nq = 25K).
__global__ void __launch_bounds__(256, 8)
k_finalize(const int4* __restrict__ v4,
           float4* __restrict__ out_v4,
           int nC4,                           // E4 copy groups (0 if unused)
           const int* __restrict__ num_nodes_ptr, int nn_fallback) {
    const int i = blockIdx.x * blockDim.x + threadIdx.x;

    if (i < nC4) {
        const int4 e = __ldcs(&v4[i]);
        __stcs(&out_v4[i],
               make_float4((float)e.x, (float)e.y, (float)e.z, (float)e.w));
    }

    const int n  = read_num_nodes(num_nodes_ptr, nn_fallback);
    const int nq = n >> 2;
    if (i < nq) {
        float4* deg4  = reinterpret_cast<float4*>(g_deg);
        float4* dinv4 = reinterpret_cast<float4*>(g_dinv);
        const float4 d = deg4[i];
        float4 r;
        r.x = (d.x > 0.0f) ? rsqrtf(d.x) : 0.0f;
        r.y = (d.y > 0.0f) ? rsqrtf(d.y) : 0.0f;
        r.z = (d.z > 0.0f) ? rsqrtf(d.z) : 0.0f;
        r.w = (d.w > 0.0f) ? rsqrtf(d.w) : 0.0f;
        dinv4[i] = r;
        deg4[i]  = make_float4(0.0f, 0.0f, 0.0f, 0.0f);
    } else if (i >= nq && i < nq + 4) {
        // scalar tail (n not divisible by 4)
        const int k = (nq << 2) + (i - nq);
        if (k < n) {
            const float d = g_deg[k];
            g_dinv[k] = (d > 0.0f) ? rsqrtf(d) : 0.0f;
            g_deg[k]  = 0.0f;
        }
    }
}

// ---------------------------------------------------------------------------
// K3 (SLIM): w_e = dinv[u] * exp(alpha*t_e) * dinv[v].
// At the gather-wavefront floor; 8 independent scattered gathers.
__global__ void __launch_bounds__(256, 8)
k_weight(const int4* __restrict__ u4,
         const int4* __restrict__ v4,
         const float4* __restrict__ t4,
         float4* __restrict__ w4, int n4) {
    const int i = blockIdx.x * blockDim.x + threadIdx.x;
    if (i >= n4) return;
    const int4   u = __ldcs(&u4[i]);
    const int4   v = __ldcs(&v4[i]);
    const float4 t = __ldcs(&t4[i]);
    const float a0 = __ldg(&g_dinv[u.x]), a1 = __ldg(&g_dinv[u.y]);
    const float a2 = __ldg(&g_dinv[u.z]), a3 = __ldg(&g_dinv[u.w]);
    const float b0 = __ldg(&g_dinv[v.x]), b1 = __ldg(&g_dinv[v.y]);
    const float b2 = __ldg(&g_dinv[v.z]), b3 = __ldg(&g_dinv[v.w]);
    float4 w;
    w.x = a0 * exp_small(TARWD_ALPHA * t.x) * b0;
    w.y = a1 * exp_small(TARWD_ALPHA * t.y) * b1;
    w.z = a2 * exp_small(TARWD_ALPHA * t.z) * b2;
    w.w = a3 * exp_small(TARWD_ALPHA * t.w) * b3;
    __stcs(&w4[i], w);
}

// ---------------------------------------------------------------------------
extern "C" void kernel_launch(void* const* d_in, const int* in_sizes, int n_in,
                              void* d_out, int out_size) {
    const int*   ei = (const int*)d_in[0];     // [2, E]: u = ei[0..E), v = ei[E..2E)
    const float* et = (const float*)d_in[1];   // [E]
    const int*   nn = (n_in >= 3) ? (const int*)d_in[2] : nullptr;
    const int    nn_fallback = 100000;

    const int E  = in_sizes[1];
    const int E4 = E >> 2;                     // E = 3.2M -> E4 = 800000
    const int* u = ei;
    const int* v = ei + E;

    float* out   = (float*)d_out;
    float* out_w = out + (out_size - E);       // weights at the tail

    const int TB = 256;
    const int GE = (E4 + TB - 1) / TB;         // 3125: exact one-shot cover

    const bool full_out = (out_size >= 3 * E); // [float(u), float(v), w]
    // copy targets: real passthrough slots, or out_w scratch (overwritten
    // afterwards by the weights) when no passthrough is required
    float* out_u = full_out ? out       : out_w;
    float* out_v = full_out ? (out + E) : out_w;
    const int nC4 = full_out ? E4 : 0;         // skip v-copy entirely if unused
    const int GF_work = (nC4 > 0) ? nC4 : (nn_fallback >> 2) + TB;
    const int GF = (GF_work + TB - 1) / TB;

    k_degree  <<<GE, TB>>>((const int4*)u, (const float4*)et,
                           (float4*)out_u, E4);
    k_finalize<<<GF, TB>>>((const int4*)v, (float4*)out_v, nC4,
                           nn, nn_fallback);
    k_weight  <<<GE, TB>>>((const int4*)u, (const int4*)v,
                           (const float4*)et, (float4*)out_w, E4);
}